// round 9
// baseline (speedup 1.0000x reference)
#include <cuda_runtime.h>
#include <cuda_fp16.h>
#include <mma.h>
#include <cstdint>

using namespace nvcuda;

#define BH      64        // batch*heads
#define SEQ     8192
#define DIM     64        // head dim
#define FEAT    128       // 2*DIM feature dim
#define NCHUNK  16
#define CHUNK   (SEQ / NCHUNK)   // 512 rows per reduction chunk
#define SUB     64               // rows staged in smem per iteration
#define BW      80               // partial width: 64 KV cols + 1 Ksum + 15 pad
#define BSW     72               // reduced B width: 64 cols + 8 pad (stride 144B)
#define OSUB    64               // out kernel: rows per sub-tile
#define ONSUB   4                // out kernel: sub-tiles per CTA

// ---- scratch (device globals: no allocation allowed) ----
__device__ float  g_kv_part[NCHUNK][BH][FEAT][BW];     // per-chunk partial [KV | Ksum | 0]
__device__ __align__(32) __half g_kvh[BH][FEAT][BSW];  // reduced fp16 B matrix (KV only)
__device__ float  g_ksum[BH][FEAT];                    // reduced fp32 Ksum

// =====================================================================
// Kernel A: partial [KV | Ksum] = phi(K)^T @ [V | 1 | 0] over a chunk
// grid (NCHUNK, BH), 256 threads. Register double-buffered pipeline.
// (unchanged from validated R4 version)
// =====================================================================
__global__ __launch_bounds__(256) void kv_partial_kernel(const float* __restrict__ Kin,
                                                         const float* __restrict__ Vin) {
    const int chunk = blockIdx.x;
    const int bh    = blockIdx.y;
    const int tid   = threadIdx.x;
    const int warp  = tid >> 5;
    const int wd    = warp >> 1;
    const int wm    = warp & 1;

    __shared__ __align__(16) __half Kf_s[SUB][136];
    __shared__ __align__(16) __half V_s [SUB][88];

    for (int r = tid; r < SUB; r += 256) {
        V_s[r][64] = __float2half(1.0f);
#pragma unroll
        for (int p = 65; p < 80; p++) V_s[r][p] = __float2half(0.0f);
    }

    wmma::fragment<wmma::accumulator, 16, 16, 16, float> acc[4];
    wmma::fragment<wmma::accumulator, 16, 16, 16, float> accs[2];
#pragma unroll
    for (int i = 0; i < 4; i++) wmma::fill_fragment(acc[i], 0.0f);
#pragma unroll
    for (int i = 0; i < 2; i++) wmma::fill_fragment(accs[i], 0.0f);

    const size_t base = ((size_t)bh * SEQ + (size_t)chunk * CHUNK) * DIM;
    const float4* __restrict__ Kp4 = (const float4*)(Kin + base);
    const float4* __restrict__ Vp4 = (const float4*)(Vin + base);

    const int NF4 = SUB * 16;
    float4 kreg[4], vreg[4];

#pragma unroll
    for (int j = 0; j < 4; j++) {
        int i = tid + j * 256;
        kreg[j] = Kp4[i];
        vreg[j] = Vp4[i];
    }

    for (int sub = 0; sub < CHUNK / SUB; ++sub) {
#pragma unroll
        for (int j = 0; j < 4; j++) {
            int i = tid + j * 256;
            int r = i >> 4, c4 = (i & 15) << 2;
            float4 k = kreg[j], v = vreg[j];
            __half2* kp = (__half2*)&Kf_s[r][c4];
            __half2* kn = (__half2*)&Kf_s[r][c4 + 64];
            __half2* vp = (__half2*)&V_s[r][c4];
            kp[0] = __floats2half2_rn(fmaxf(k.x, 0.f), fmaxf(k.y, 0.f));
            kp[1] = __floats2half2_rn(fmaxf(k.z, 0.f), fmaxf(k.w, 0.f));
            kn[0] = __floats2half2_rn(fmaxf(-k.x, 0.f), fmaxf(-k.y, 0.f));
            kn[1] = __floats2half2_rn(fmaxf(-k.z, 0.f), fmaxf(-k.w, 0.f));
            vp[0] = __floats2half2_rn(v.x, v.y);
            vp[1] = __floats2half2_rn(v.z, v.w);
        }
        __syncthreads();

        if (sub + 1 < CHUNK / SUB) {
#pragma unroll
            for (int j = 0; j < 4; j++) {
                int i = tid + j * 256;
                kreg[j] = Kp4[(sub + 1) * NF4 + i];
                vreg[j] = Vp4[(sub + 1) * NF4 + i];
            }
        }

#pragma unroll
        for (int ks = 0; ks < SUB / 16; ++ks) {
            wmma::fragment<wmma::matrix_a, 16, 16, 16, __half, wmma::col_major> a0, a1;
            wmma::fragment<wmma::matrix_b, 16, 16, 16, __half, wmma::row_major> b0, b1;
            wmma::load_matrix_sync(a0, &Kf_s[ks * 16][wd * 32],      136);
            wmma::load_matrix_sync(a1, &Kf_s[ks * 16][wd * 32 + 16], 136);
            wmma::load_matrix_sync(b0, &V_s[ks * 16][wm * 32],       88);
            wmma::load_matrix_sync(b1, &V_s[ks * 16][wm * 32 + 16],  88);
            wmma::mma_sync(acc[0], a0, b0, acc[0]);
            wmma::mma_sync(acc[1], a0, b1, acc[1]);
            wmma::mma_sync(acc[2], a1, b0, acc[2]);
            wmma::mma_sync(acc[3], a1, b1, acc[3]);
            if (wm == 0) {
                wmma::fragment<wmma::matrix_b, 16, 16, 16, __half, wmma::row_major> b2;
                wmma::load_matrix_sync(b2, &V_s[ks * 16][64], 88);
                wmma::mma_sync(accs[0], a0, b2, accs[0]);
                wmma::mma_sync(accs[1], a1, b2, accs[1]);
            }
        }
        __syncthreads();
    }

    float* op = &g_kv_part[chunk][bh][0][0];
#pragma unroll
    for (int ti = 0; ti < 2; ++ti)
#pragma unroll
        for (int tj = 0; tj < 2; ++tj)
            wmma::store_matrix_sync(op + (wd * 32 + ti * 16) * BW + wm * 32 + tj * 16,
                                    acc[ti * 2 + tj], BW, wmma::mem_row_major);
    if (wm == 0) {
        wmma::store_matrix_sync(op + (wd * 32) * BW + 64,      accs[0], BW, wmma::mem_row_major);
        wmma::store_matrix_sync(op + (wd * 32 + 16) * BW + 64, accs[1], BW, wmma::mem_row_major);
    }
}

// =====================================================================
// Kernel B: reduce chunk partials -> fp16 B matrix [128 x 72] + fp32 Ksum
// grid (BH, 8): each block handles 16 feature rows
// =====================================================================
__global__ __launch_bounds__(256) void kv_reduce_kernel() {
    const int bh    = blockIdx.x;
    const int dbase = blockIdx.y * 16;
    const int tid   = threadIdx.x;

    for (int idx = tid; idx < 16 * 64; idx += 256) {
        int d = dbase + (idx >> 6), m = idx & 63;
        float s = 0.0f;
#pragma unroll
        for (int c = 0; c < NCHUNK; c++) s += g_kv_part[c][bh][d][m];
        g_kvh[bh][d][m] = __float2half(s);
    }
    for (int idx = tid; idx < 16 * 8; idx += 256) {   // zero pad cols 64..71
        int d = dbase + (idx >> 3), m = 64 + (idx & 7);
        g_kvh[bh][d][m] = __float2half(0.0f);
    }
    if (tid < 16) {
        int d = dbase + tid;
        float s = 0.0f;
#pragma unroll
        for (int c = 0; c < NCHUNK; c++) s += g_kv_part[c][bh][d][64];
        g_ksum[bh][d] = s;
    }
}

// =====================================================================
// Kernel C: out = (phi(Q) @ KV) * 1/(phi(Q)·Ksum + eps), raw mma.sync,
// fragment-level scaled epilogue, direct STG. grid (SEQ/256, BH), 256 thr.
// Warp w: row-group rg=w>>1 (16 rows), col-half ch=w&1 (32 cols).
// =====================================================================
__global__ __launch_bounds__(256) void out_kernel(const float* __restrict__ Qin,
                                                  float* __restrict__ Out) {
    const int nt   = blockIdx.x;
    const int bh   = blockIdx.y;
    const int tid  = threadIdx.x;
    const int warp = tid >> 5;
    const int lane = tid & 31;

    __shared__ __align__(16) __half qf[2][OSUB][136];   // 34816 B (double buffered)
    __shared__ __align__(16) __half Bs[FEAT][BSW];      // 18432 B
    __shared__ float nsm[2][OSUB];                      // 1/(normalizer+eps)
    __shared__ float ksF[FEAT];

    const size_t qbase = ((size_t)bh * SEQ + (size_t)nt * (OSUB * ONSUB)) * DIM;
    const float4* __restrict__ Qp4 = (const float4*)(Qin + qbase);
    float* __restrict__ Op = Out + qbase;

    // stage B (1152 uint4) + fp32 Ksum once per CTA
    {
        const uint4* __restrict__ Bg = (const uint4*)&g_kvh[bh][0][0];
        uint4* Bsv = (uint4*)&Bs[0][0];
        for (int i = tid; i < FEAT * BSW * 2 / 16; i += 256) Bsv[i] = Bg[i];
        if (tid < FEAT) ksF[tid] = g_ksum[bh][tid];
    }

    float4 qreg[4];
#pragma unroll
    for (int j = 0; j < 4; j++) qreg[j] = Qp4[tid + j * 256];

    const int rg = warp >> 1;      // 16-row group
    const int ch = warp & 1;       // 32-col half
    const int g  = lane >> 2;      // mma group id (row within tile)
    const int tq = lane & 3;       // thread-in-group (col pair)

    for (int s = 0; s < ONSUB; ++s) {
        const int p = s & 1;
        // ---- convert qreg -> qf[p] (phi transform) ----
#pragma unroll
        for (int j = 0; j < 4; j++) {
            int i = tid + j * 256;
            int r = i >> 4, c4 = (i & 15) << 2;
            float4 q = qreg[j];
            __half2* qp = (__half2*)&qf[p][r][c4];
            __half2* qn = (__half2*)&qf[p][r][c4 + 64];
            qp[0] = __floats2half2_rn(fmaxf(q.x, 0.f), fmaxf(q.y, 0.f));
            qp[1] = __floats2half2_rn(fmaxf(q.z, 0.f), fmaxf(q.w, 0.f));
            qn[0] = __floats2half2_rn(fmaxf(-q.x, 0.f), fmaxf(-q.y, 0.f));
            qn[1] = __floats2half2_rn(fmaxf(-q.z, 0.f), fmaxf(-q.w, 0.f));
        }
        __syncthreads();

        // prefetch next sub-tile's Q (hides under normalizer + MMA)
        if (s + 1 < ONSUB) {
#pragma unroll
            for (int j = 0; j < 4; j++)
                qreg[j] = Qp4[(s + 1) * (OSUB * 16) + tid + j * 256];
        }

        // ---- normalizer: 4 threads per row, fp32 accumulate ----
        {
            int row = tid >> 2, part = tid & 3;
            const __half2* qrow = (const __half2*)&qf[p][row][part * 32];
            float sum = 0.0f;
#pragma unroll
            for (int d2 = 0; d2 < 16; d2++) {
                float2 v = __half22float2(qrow[d2]);
                sum += v.x * ksF[part * 32 + 2 * d2] + v.y * ksF[part * 32 + 2 * d2 + 1];
            }
            sum += __shfl_xor_sync(0xffffffffu, sum, 1);
            sum += __shfl_xor_sync(0xffffffffu, sum, 2);
            if (part == 0) nsm[p][row] = 1.0f / (sum + 1e-6f);
        }
        __syncthreads();

        // ---- MMA: 16x32 tile per warp over k=128 ----
        float c[4][4];
#pragma unroll
        for (int f = 0; f < 4; f++)
#pragma unroll
            for (int e = 0; e < 4; e++) c[f][e] = 0.0f;

#pragma unroll
        for (int ks = 0; ks < FEAT / 16; ++ks) {
            uint32_t a[4];
            {
                uint32_t addr = (uint32_t)__cvta_generic_to_shared(
                    &qf[p][rg * 16 + (lane & 15)][ks * 16 + (lane >> 4) * 8]);
                asm volatile("ldmatrix.sync.aligned.m8n8.x4.shared.b16 {%0,%1,%2,%3}, [%4];"
                             : "=r"(a[0]), "=r"(a[1]), "=r"(a[2]), "=r"(a[3]) : "r"(addr));
            }
#pragma unroll
            for (int h = 0; h < 2; h++) {
                uint32_t b[4];
                uint32_t addr = (uint32_t)__cvta_generic_to_shared(
                    &Bs[ks * 16 + (lane & 15)][ch * 32 + h * 16 + (lane >> 4) * 8]);
                asm volatile("ldmatrix.sync.aligned.m8n8.x4.trans.shared.b16 {%0,%1,%2,%3}, [%4];"
                             : "=r"(b[0]), "=r"(b[1]), "=r"(b[2]), "=r"(b[3]) : "r"(addr));
                asm volatile("mma.sync.aligned.m16n8k16.row.col.f32.f16.f16.f32 "
                             "{%0,%1,%2,%3},{%4,%5,%6,%7},{%8,%9},{%0,%1,%2,%3};"
                             : "+f"(c[h*2][0]), "+f"(c[h*2][1]), "+f"(c[h*2][2]), "+f"(c[h*2][3])
                             : "r"(a[0]), "r"(a[1]), "r"(a[2]), "r"(a[3]), "r"(b[0]), "r"(b[1]));
                asm volatile("mma.sync.aligned.m16n8k16.row.col.f32.f16.f16.f32 "
                             "{%0,%1,%2,%3},{%4,%5,%6,%7},{%8,%9},{%0,%1,%2,%3};"
                             : "+f"(c[h*2+1][0]), "+f"(c[h*2+1][1]), "+f"(c[h*2+1][2]), "+f"(c[h*2+1][3])
                             : "r"(a[0]), "r"(a[1]), "r"(a[2]), "r"(a[3]), "r"(b[2]), "r"(b[3]));
            }
        }

        // ---- epilogue: scale in-register, STG.64 direct to global ----
        {
            float ilo = nsm[p][rg * 16 + g];
            float ihi = nsm[p][rg * 16 + 8 + g];
            int r0 = s * OSUB + rg * 16 + g;
#pragma unroll
            for (int f = 0; f < 4; f++) {
                int col = ch * 32 + f * 8 + 2 * tq;
                float2 lo = make_float2(c[f][0] * ilo, c[f][1] * ilo);
                float2 hi = make_float2(c[f][2] * ihi, c[f][3] * ihi);
                *(float2*)&Op[(size_t)r0 * DIM + col]       = lo;
                *(float2*)&Op[(size_t)(r0 + 8) * DIM + col] = hi;
            }
        }
        // no extra sync: next convert writes qf[1-p]; nsm[1-p] written only
        // after the next barrier, by which point these epilogue reads are done.
    }
}

// =====================================================================
extern "C" void kernel_launch(void* const* d_in, const int* in_sizes, int n_in,
                              void* d_out, int out_size) {
    const float* Q = (const float*)d_in[0];
    const float* K = (const float*)d_in[1];
    const float* V = (const float*)d_in[2];
    float* O = (float*)d_out;

    dim3 gA(NCHUNK, BH);
    kv_partial_kernel<<<gA, 256>>>(K, V);
    dim3 gB(BH, 8);
    kv_reduce_kernel<<<gB, 256>>>();
    dim3 gC(SEQ / (OSUB * ONSUB), BH);
    out_kernel<<<gC, 256>>>(Q, O);
}

// round 12
// speedup vs baseline: 1.1714x; 1.1714x over previous
#include <cuda_runtime.h>
#include <cuda_fp16.h>
#include <mma.h>
#include <cstdint>

using namespace nvcuda;

#define BH      64        // batch*heads
#define SEQ     8192
#define DIM     64        // head dim
#define FEAT    128       // 2*DIM feature dim
#define NCHUNK  16
#define CHUNK   (SEQ / NCHUNK)   // 512 rows per reduction chunk
#define SUB     64               // rows staged in smem per iteration
#define BW      80               // partial width: 64 KV cols + 1 Ksum + 15 pad
#define BSW     88               // reduced B width: 64 KV + col64 Ksum + pad (stride 176B, conflict-free)
#define ONS     2                // out kernel: 128-row super-tiles per CTA

// ---- scratch (device globals: no allocation allowed) ----
__device__ float  g_kv_part[NCHUNK][BH][FEAT][BW];     // per-chunk partial [KV | Ksum | 0]
__device__ __align__(32) __half g_kvh[BH][FEAT][BSW];  // reduced fp16 B (col64 = Ksum)

// =====================================================================
// Kernel A: partial [KV | Ksum] = phi(K)^T @ [V | 1 | 0] over a chunk
// grid (NCHUNK, BH), 256 threads. Register double-buffered pipeline.
// (unchanged from validated R4/R7 version)
// =====================================================================
__global__ __launch_bounds__(256) void kv_partial_kernel(const float* __restrict__ Kin,
                                                         const float* __restrict__ Vin) {
    const int chunk = blockIdx.x;
    const int bh    = blockIdx.y;
    const int tid   = threadIdx.x;
    const int warp  = tid >> 5;
    const int wd    = warp >> 1;
    const int wm    = warp & 1;

    __shared__ __align__(16) __half Kf_s[SUB][136];
    __shared__ __align__(16) __half V_s [SUB][88];

    for (int r = tid; r < SUB; r += 256) {
        V_s[r][64] = __float2half(1.0f);
#pragma unroll
        for (int p = 65; p < 80; p++) V_s[r][p] = __float2half(0.0f);
    }

    wmma::fragment<wmma::accumulator, 16, 16, 16, float> acc[4];
    wmma::fragment<wmma::accumulator, 16, 16, 16, float> accs[2];
#pragma unroll
    for (int i = 0; i < 4; i++) wmma::fill_fragment(acc[i], 0.0f);
#pragma unroll
    for (int i = 0; i < 2; i++) wmma::fill_fragment(accs[i], 0.0f);

    const size_t base = ((size_t)bh * SEQ + (size_t)chunk * CHUNK) * DIM;
    const float4* __restrict__ Kp4 = (const float4*)(Kin + base);
    const float4* __restrict__ Vp4 = (const float4*)(Vin + base);

    const int NF4 = SUB * 16;
    float4 kreg[4], vreg[4];

#pragma unroll
    for (int j = 0; j < 4; j++) {
        int i = tid + j * 256;
        kreg[j] = Kp4[i];
        vreg[j] = Vp4[i];
    }

    for (int sub = 0; sub < CHUNK / SUB; ++sub) {
#pragma unroll
        for (int j = 0; j < 4; j++) {
            int i = tid + j * 256;
            int r = i >> 4, c4 = (i & 15) << 2;
            float4 k = kreg[j], v = vreg[j];
            __half2* kp = (__half2*)&Kf_s[r][c4];
            __half2* kn = (__half2*)&Kf_s[r][c4 + 64];
            __half2* vp = (__half2*)&V_s[r][c4];
            kp[0] = __floats2half2_rn(fmaxf(k.x, 0.f), fmaxf(k.y, 0.f));
            kp[1] = __floats2half2_rn(fmaxf(k.z, 0.f), fmaxf(k.w, 0.f));
            kn[0] = __floats2half2_rn(fmaxf(-k.x, 0.f), fmaxf(-k.y, 0.f));
            kn[1] = __floats2half2_rn(fmaxf(-k.z, 0.f), fmaxf(-k.w, 0.f));
            vp[0] = __floats2half2_rn(v.x, v.y);
            vp[1] = __floats2half2_rn(v.z, v.w);
        }
        __syncthreads();

        if (sub + 1 < CHUNK / SUB) {
#pragma unroll
            for (int j = 0; j < 4; j++) {
                int i = tid + j * 256;
                kreg[j] = Kp4[(sub + 1) * NF4 + i];
                vreg[j] = Vp4[(sub + 1) * NF4 + i];
            }
        }

#pragma unroll
        for (int ks = 0; ks < SUB / 16; ++ks) {
            wmma::fragment<wmma::matrix_a, 16, 16, 16, __half, wmma::col_major> a0, a1;
            wmma::fragment<wmma::matrix_b, 16, 16, 16, __half, wmma::row_major> b0, b1;
            wmma::load_matrix_sync(a0, &Kf_s[ks * 16][wd * 32],      136);
            wmma::load_matrix_sync(a1, &Kf_s[ks * 16][wd * 32 + 16], 136);
            wmma::load_matrix_sync(b0, &V_s[ks * 16][wm * 32],       88);
            wmma::load_matrix_sync(b1, &V_s[ks * 16][wm * 32 + 16],  88);
            wmma::mma_sync(acc[0], a0, b0, acc[0]);
            wmma::mma_sync(acc[1], a0, b1, acc[1]);
            wmma::mma_sync(acc[2], a1, b0, acc[2]);
            wmma::mma_sync(acc[3], a1, b1, acc[3]);
            if (wm == 0) {
                wmma::fragment<wmma::matrix_b, 16, 16, 16, __half, wmma::row_major> b2;
                wmma::load_matrix_sync(b2, &V_s[ks * 16][64], 88);
                wmma::mma_sync(accs[0], a0, b2, accs[0]);
                wmma::mma_sync(accs[1], a1, b2, accs[1]);
            }
        }
        __syncthreads();
    }

    float* op = &g_kv_part[chunk][bh][0][0];
#pragma unroll
    for (int ti = 0; ti < 2; ++ti)
#pragma unroll
        for (int tj = 0; tj < 2; ++tj)
            wmma::store_matrix_sync(op + (wd * 32 + ti * 16) * BW + wm * 32 + tj * 16,
                                    acc[ti * 2 + tj], BW, wmma::mem_row_major);
    if (wm == 0) {
        wmma::store_matrix_sync(op + (wd * 32) * BW + 64,      accs[0], BW, wmma::mem_row_major);
        wmma::store_matrix_sync(op + (wd * 32 + 16) * BW + 64, accs[1], BW, wmma::mem_row_major);
    }
}

// =====================================================================
// Kernel B: reduce chunk partials -> fp16 B matrix [128 x 88]
// (cols 0..63 = KV, col 64 = Ksum, 65..87 = 0). grid (BH, 8), 256 thr.
// =====================================================================
__global__ __launch_bounds__(256) void kv_reduce_kernel() {
    const int bh    = blockIdx.x;
    const int dbase = blockIdx.y * 16;
    const int tid   = threadIdx.x;

    for (int idx = tid; idx < 16 * 64; idx += 256) {
        int d = dbase + (idx >> 6), m = idx & 63;
        float s = 0.0f;
#pragma unroll
        for (int c = 0; c < NCHUNK; c++) s += g_kv_part[c][bh][d][m];
        g_kvh[bh][d][m] = __float2half(s);
    }
    if (tid < 16) {
        int d = dbase + tid;
        float s = 0.0f;
#pragma unroll
        for (int c = 0; c < NCHUNK; c++) s += g_kv_part[c][bh][d][64];
        g_kvh[bh][d][64] = __float2half(s);
    }
    for (int idx = tid; idx < 16 * 23; idx += 256) {   // zero cols 65..87
        int d = dbase + idx / 23, m = 65 + idx % 23;
        g_kvh[bh][d][m] = __float2half(0.0f);
    }
}

// =====================================================================
// Kernel C: warp-autonomous. 256 threads = 8 warps; warp w owns rows
// [w*16, w*16+16) of a 128-row super-tile, ALL 72 cols (incl. Ksum col).
// Only 2 __syncthreads per super-tile. grid (SEQ/(128*ONS), BH).
// Dynamic smem: qf[128][136] fp16 | Bs[128][88] fp16 | cs 8x[16][68] fp32
// =====================================================================
#define QF_BYTES  (128 * 136 * 2)   // 34816
#define BS_BYTES  (128 * BSW * 2)   // 22528
#define CS_STRIDE 68
#define CS_BYTES  (8 * 16 * CS_STRIDE * 4)  // 34816
#define C_SMEM    (QF_BYTES + BS_BYTES + CS_BYTES)   // 92160

__global__ __launch_bounds__(256) void out_kernel(const float* __restrict__ Qin,
                                                  float* __restrict__ Out) {
    extern __shared__ __align__(16) char sm[];
    __half (*qf)[136] = reinterpret_cast<__half(*)[136]>(sm);
    __half (*Bs)[BSW] = reinterpret_cast<__half(*)[BSW]>(sm + QF_BYTES);
    float*  csAll     = reinterpret_cast<float*>(sm + QF_BYTES + BS_BYTES);

    const int nt   = blockIdx.x;
    const int bh   = blockIdx.y;
    const int tid  = threadIdx.x;
    const int warp = tid >> 5;
    const int lane = tid & 31;
    const int g    = lane >> 2;     // row within 8-row mma group
    const int tq   = lane & 3;      // col-pair within n8 tile

    float* cw = csAll + warp * 16 * CS_STRIDE;   // private 16x68 strip

    const size_t qbase = ((size_t)bh * SEQ + (size_t)nt * (128 * ONS)) * DIM;
    const float4* __restrict__ Qp4 = (const float4*)(Qin + qbase);
    float* __restrict__ Op = Out + qbase;

    // stage B once per CTA (coalesced uint4)
    {
        const uint4* __restrict__ Bg = (const uint4*)&g_kvh[bh][0][0];
        uint4* Bsv = (uint4*)&Bs[0][0];
        for (int i = tid; i < BS_BYTES / 16; i += 256) Bsv[i] = Bg[i];
    }

    float4 qreg[8];
#pragma unroll
    for (int j = 0; j < 8; j++) qreg[j] = Qp4[tid + j * 256];

    for (int s = 0; s < ONS; ++s) {
        // ---- convert qreg -> qf (phi transform), 128 rows ----
#pragma unroll
        for (int j = 0; j < 8; j++) {
            int i = tid + j * 256;
            int r = i >> 4, c4 = (i & 15) << 2;
            float4 q = qreg[j];
            __half2* qp = (__half2*)&qf[r][c4];
            __half2* qn = (__half2*)&qf[r][c4 + 64];
            qp[0] = __floats2half2_rn(fmaxf(q.x, 0.f), fmaxf(q.y, 0.f));
            qp[1] = __floats2half2_rn(fmaxf(q.z, 0.f), fmaxf(q.w, 0.f));
            qn[0] = __floats2half2_rn(fmaxf(-q.x, 0.f), fmaxf(-q.y, 0.f));
            qn[1] = __floats2half2_rn(fmaxf(-q.z, 0.f), fmaxf(-q.w, 0.f));
        }
        __syncthreads();   // qf ready (and prior iter's qf readers done)

        // prefetch next super-tile's Q; lands during the long MMA stretch
        if (s + 1 < ONS) {
#pragma unroll
            for (int j = 0; j < 8; j++)
                qreg[j] = Qp4[(s + 1) * 2048 + tid + j * 256];
        }

        // ---- warp-local: MMA 16 rows x 72 cols over k=128 ----
        float c[9][4];
#pragma unroll
        for (int f = 0; f < 9; f++)
#pragma unroll
            for (int e = 0; e < 4; e++) c[f][e] = 0.0f;

#pragma unroll
        for (int ks = 0; ks < FEAT / 16; ++ks) {
            uint32_t a[4];
            {
                uint32_t addr = (uint32_t)__cvta_generic_to_shared(
                    &qf[warp * 16 + (lane & 15)][ks * 16 + (lane >> 4) * 8]);
                asm volatile("ldmatrix.sync.aligned.m8n8.x4.shared.b16 {%0,%1,%2,%3}, [%4];"
                             : "=r"(a[0]), "=r"(a[1]), "=r"(a[2]), "=r"(a[3]) : "r"(addr));
            }
#pragma unroll
            for (int h = 0; h < 4; h++) {   // cols 0..63 in 16-col pairs
                uint32_t b[4];
                uint32_t addr = (uint32_t)__cvta_generic_to_shared(
                    &Bs[ks * 16 + (lane & 15)][h * 16 + (lane >> 4) * 8]);
                asm volatile("ldmatrix.sync.aligned.m8n8.x4.trans.shared.b16 {%0,%1,%2,%3}, [%4];"
                             : "=r"(b[0]), "=r"(b[1]), "=r"(b[2]), "=r"(b[3]) : "r"(addr));
                asm volatile("mma.sync.aligned.m16n8k16.row.col.f32.f16.f16.f32 "
                             "{%0,%1,%2,%3},{%4,%5,%6,%7},{%8,%9},{%0,%1,%2,%3};"
                             : "+f"(c[h*2][0]), "+f"(c[h*2][1]), "+f"(c[h*2][2]), "+f"(c[h*2][3])
                             : "r"(a[0]), "r"(a[1]), "r"(a[2]), "r"(a[3]), "r"(b[0]), "r"(b[1]));
                asm volatile("mma.sync.aligned.m16n8k16.row.col.f32.f16.f16.f32 "
                             "{%0,%1,%2,%3},{%4,%5,%6,%7},{%8,%9},{%0,%1,%2,%3};"
                             : "+f"(c[h*2+1][0]), "+f"(c[h*2+1][1]), "+f"(c[h*2+1][2]), "+f"(c[h*2+1][3])
                             : "r"(a[0]), "r"(a[1]), "r"(a[2]), "r"(a[3]), "r"(b[2]), "r"(b[3]));
            }
            {   // Ksum tile: cols 64..71 (col 64 = normalizer, 65..71 zero)
                uint32_t b[2];
                uint32_t addr = (uint32_t)__cvta_generic_to_shared(
                    &Bs[ks * 16 + (lane & 15)][64]);
                asm volatile("ldmatrix.sync.aligned.m8n8.x2.trans.shared.b16 {%0,%1}, [%2];"
                             : "=r"(b[0]), "=r"(b[1]) : "r"(addr));
                asm volatile("mma.sync.aligned.m16n8k16.row.col.f32.f16.f16.f32 "
                             "{%0,%1,%2,%3},{%4,%5,%6,%7},{%8,%9},{%0,%1,%2,%3};"
                             : "+f"(c[8][0]), "+f"(c[8][1]), "+f"(c[8][2]), "+f"(c[8][3])
                             : "r"(a[0]), "r"(a[1]), "r"(a[2]), "r"(a[3]), "r"(b[0]), "r"(b[1]));
            }
        }

        // ---- normalizer from own accumulators (col 64 held by tq==0) ----
        float n_lo = __shfl_sync(0xffffffffu, c[8][0], lane & ~3);
        float n_hi = __shfl_sync(0xffffffffu, c[8][2], lane & ~3);
        float inv_lo = 1.0f / (n_lo + 1e-6f);
        float inv_hi = 1.0f / (n_hi + 1e-6f);

        // ---- scale in-register, bounce through private cs strip ----
#pragma unroll
        for (int f = 0; f < 8; f++) {
            int col = f * 8 + 2 * tq;
            *(float2*)&cw[g * CS_STRIDE + col] =
                make_float2(c[f][0] * inv_lo, c[f][1] * inv_lo);
            *(float2*)&cw[(g + 8) * CS_STRIDE + col] =
                make_float2(c[f][2] * inv_hi, c[f][3] * inv_hi);
        }
        __syncwarp();

        // ---- coalesced float4 read-back + STG (16 rows x 256B contiguous) ----
        {
            float* orow = Op + ((size_t)s * 128 + warp * 16) * DIM;
#pragma unroll
            for (int it = 0; it < 8; ++it) {
                int idx = lane + it * 32;
                int r = idx >> 4, c4 = (idx & 15) << 2;
                float4 v = *(float4*)&cw[r * CS_STRIDE + c4];
                *(float4*)&orow[(size_t)r * DIM + c4] = v;
            }
        }
        __syncthreads();   // all warps done with qf before next convert
    }
}

// =====================================================================
extern "C" void kernel_launch(void* const* d_in, const int* in_sizes, int n_in,
                              void* d_out, int out_size) {
    const float* Q = (const float*)d_in[0];
    const float* K = (const float*)d_in[1];
    const float* V = (const float*)d_in[2];
    float* O = (float*)d_out;

    static int smem_set = 0;
    if (!smem_set) {
        cudaFuncSetAttribute(out_kernel, cudaFuncAttributeMaxDynamicSharedMemorySize, C_SMEM);
        smem_set = 1;
    }

    dim3 gA(NCHUNK, BH);
    kv_partial_kernel<<<gA, 256>>>(K, V);
    dim3 gB(BH, 8);
    kv_reduce_kernel<<<gB, 256>>>();
    dim3 gC(SEQ / (128 * ONS), BH);
    out_kernel<<<gC, 256, C_SMEM>>>(Q, O);
}